// round 1
// baseline (speedup 1.0000x reference)
#include <cuda_runtime.h>
#include <math.h>

#define B_ 4
#define N_ 4096
#define D_ 128

// ---------------- scratch (device globals; no runtime allocation) ----------
__device__ float g_q[B_ * N_ * D_];
__device__ float g_k[B_ * N_ * D_];
__device__ float g_v[B_ * N_ * D_];
__device__ float g_att[B_ * N_ * D_];
__device__ float g_h[B_ * N_ * D_];

// ---------------------------------------------------------------------------
// Generic GEMM: Y[M,128] = act(X[M,128] @ W^T[128,128] + b) (+ resid)
// Block: 128 rows x 128 cols, 256 threads, 8x8 per-thread tile.
// Smem: Xs natural [128][128], Wt k-major [128][128].
// ---------------------------------------------------------------------------
__global__ __launch_bounds__(256) void gemm128(
    const float* __restrict__ X, const float* __restrict__ W,
    const float* __restrict__ bias, const float* __restrict__ resid,
    float* __restrict__ Y, int do_relu)
{
    extern __shared__ float sm[];
    float* Xs = sm;               // 128*128
    float* Wt = sm + 128 * 128;   // 128*128, k-major: Wt[k][j] = W[j][k]

    const int tid = threadIdx.x;
    const int ty = tid >> 4;      // 0..15 -> rows ty*8..+7
    const int tx = tid & 15;      // 0..15 -> cols tx*8..+7
    const int row0 = blockIdx.x * 128;

    // Load X tile (natural, coalesced)
    {
        const float4* Xg = reinterpret_cast<const float4*>(X + (size_t)row0 * D_);
        float4* Xs4 = reinterpret_cast<float4*>(Xs);
#pragma unroll
        for (int it = 0; it < 16; ++it) {
            int idx = tid + it * 256;     // 4096 float4
            Xs4[idx] = Xg[idx];
        }
    }
    // Load W transposed into Wt (k-major)
    {
        const float4* Wg = reinterpret_cast<const float4*>(W);
#pragma unroll
        for (int it = 0; it < 16; ++it) {
            int idx = tid + it * 256;     // 4096 float4
            int j  = idx & 127;
            int kq = idx >> 7;            // float4 index along k: 0..31
            float4 w = Wg[(size_t)j * 32 + kq];
            Wt[(kq * 4 + 0) * 128 + j] = w.x;
            Wt[(kq * 4 + 1) * 128 + j] = w.y;
            Wt[(kq * 4 + 2) * 128 + j] = w.z;
            Wt[(kq * 4 + 3) * 128 + j] = w.w;
        }
    }
    __syncthreads();

    float acc[8][8];
#pragma unroll
    for (int i = 0; i < 8; ++i)
#pragma unroll
        for (int j = 0; j < 8; ++j) acc[i][j] = 0.f;

    const float4* Xs4 = reinterpret_cast<const float4*>(Xs);
    const float4* Wt4 = reinterpret_cast<const float4*>(Wt);

    for (int kq = 0; kq < 32; ++kq) {
        float4 xa[8];
#pragma unroll
        for (int i = 0; i < 8; ++i) xa[i] = Xs4[(ty * 8 + i) * 32 + kq];
#pragma unroll
        for (int kk = 0; kk < 4; ++kk) {
            int k = kq * 4 + kk;
            float4 w0 = Wt4[k * 32 + tx * 2];
            float4 w1 = Wt4[k * 32 + tx * 2 + 1];
#pragma unroll
            for (int i = 0; i < 8; ++i) {
                float a = reinterpret_cast<const float*>(&xa[i])[kk];
                acc[i][0] += a * w0.x; acc[i][1] += a * w0.y;
                acc[i][2] += a * w0.z; acc[i][3] += a * w0.w;
                acc[i][4] += a * w1.x; acc[i][5] += a * w1.y;
                acc[i][6] += a * w1.z; acc[i][7] += a * w1.w;
            }
        }
    }

    // Epilogue
    float bb[8];
    {
        float4 b0 = *reinterpret_cast<const float4*>(bias + tx * 8);
        float4 b1 = *reinterpret_cast<const float4*>(bias + tx * 8 + 4);
        bb[0] = b0.x; bb[1] = b0.y; bb[2] = b0.z; bb[3] = b0.w;
        bb[4] = b1.x; bb[5] = b1.y; bb[6] = b1.z; bb[7] = b1.w;
    }
#pragma unroll
    for (int i = 0; i < 8; ++i) {
        int row = row0 + ty * 8 + i;
        float v[8];
#pragma unroll
        for (int j = 0; j < 8; ++j) {
            float val = acc[i][j] + bb[j];
            if (do_relu) val = fmaxf(val, 0.f);
            v[j] = val;
        }
        if (resid) {
            const float4* rg = reinterpret_cast<const float4*>(resid + (size_t)row * D_ + tx * 8);
            float4 r0 = rg[0], r1 = rg[1];
            v[0] += r0.x; v[1] += r0.y; v[2] += r0.z; v[3] += r0.w;
            v[4] += r1.x; v[5] += r1.y; v[6] += r1.z; v[7] += r1.w;
        }
        float4* yg = reinterpret_cast<float4*>(Y + (size_t)row * D_ + tx * 8);
        yg[0] = make_float4(v[0], v[1], v[2], v[3]);
        yg[1] = make_float4(v[4], v[5], v[6], v[7]);
    }
}

// ---------------------------------------------------------------------------
// Fused attention: for one (batch, 64-row q tile):
//   S = Q K^T * scale + eye + adj ; online softmax ; O += P V ; out = relu(O/l)+x
// Smem: Qt [128][64] k-major, Kt [128][64] k-major (aliased by Pt [64][68]),
//       Vs [64][128] natural. 96 KB -> 2 CTAs/SM.
// ---------------------------------------------------------------------------
__global__ __launch_bounds__(256, 2) void attn128(
    const float* __restrict__ Q, const float* __restrict__ K,
    const float* __restrict__ V, const float* __restrict__ adj,
    const float* __restrict__ X, float* __restrict__ Out)
{
    extern __shared__ float sm[];
    float* Qt  = sm;            // 8192 floats
    float* KtP = sm + 8192;     // 8192 floats; Kt (k-major) aliased by Pt[64][68]
    float* Vs  = sm + 16384;    // 8192 floats

    const int tid = threadIdx.x;
    const int ty = tid >> 4;    // 0..15 -> q rows ty*4..+3
    const int tx = tid & 15;    // 0..15 -> kv cols tx*4..+3 (S), d cols tx*8..+7 (O)
    const int b  = blockIdx.y;
    const int r0 = blockIdx.x * 64;

    // Load Q tile transposed (k-major)
    {
        const float4* Qg = reinterpret_cast<const float4*>(Q + ((size_t)b * N_ + r0) * D_);
#pragma unroll
        for (int it = 0; it < 8; ++it) {
            int idx = tid + it * 256;   // 2048 float4
            int r = idx & 63, kq = idx >> 6;
            float4 v4 = Qg[r * 32 + kq];
            Qt[(kq * 4 + 0) * 64 + r] = v4.x;
            Qt[(kq * 4 + 1) * 64 + r] = v4.y;
            Qt[(kq * 4 + 2) * 64 + r] = v4.z;
            Qt[(kq * 4 + 3) * 64 + r] = v4.w;
        }
    }

    float m_[4], l_[4], Oa[4][8];
#pragma unroll
    for (int i = 0; i < 4; ++i) { m_[i] = -1e30f; l_[i] = 0.f; }
#pragma unroll
    for (int i = 0; i < 4; ++i)
#pragma unroll
        for (int c = 0; c < 8; ++c) Oa[i][c] = 0.f;

    const float scale = 0.088388347648318447f;   // 1/sqrt(128)
    const float LOG2E = 1.4426950408889634f;

    for (int ct = 0; ct < N_ / 64; ++ct) {
        __syncthreads();   // prev iter's PV reads of Vs/Pt complete
        {
            const float4* Kg = reinterpret_cast<const float4*>(K + ((size_t)b * N_ + ct * 64) * D_);
            const float4* Vg = reinterpret_cast<const float4*>(V + ((size_t)b * N_ + ct * 64) * D_);
            float4* Vs4 = reinterpret_cast<float4*>(Vs);
#pragma unroll
            for (int it = 0; it < 8; ++it) {
                int idx = tid + it * 256;
                int r = idx & 63, kq = idx >> 6;
                float4 v4 = Kg[r * 32 + kq];
                KtP[(kq * 4 + 0) * 64 + r] = v4.x;
                KtP[(kq * 4 + 1) * 64 + r] = v4.y;
                KtP[(kq * 4 + 2) * 64 + r] = v4.z;
                KtP[(kq * 4 + 3) * 64 + r] = v4.w;
                Vs4[idx] = Vg[idx];
            }
        }
        __syncthreads();

        // S = Q K^T (4x4 per thread)
        float s[4][4];
#pragma unroll
        for (int i = 0; i < 4; ++i)
#pragma unroll
            for (int j = 0; j < 4; ++j) s[i][j] = 0.f;

        const float4* Qt4 = reinterpret_cast<const float4*>(Qt);
        const float4* Kt4 = reinterpret_cast<const float4*>(KtP);
#pragma unroll 8
        for (int k = 0; k < 128; ++k) {
            float4 a  = Qt4[k * 16 + ty];
            float4 bb = Kt4[k * 16 + tx];
            s[0][0] += a.x * bb.x; s[0][1] += a.x * bb.y; s[0][2] += a.x * bb.z; s[0][3] += a.x * bb.w;
            s[1][0] += a.y * bb.x; s[1][1] += a.y * bb.y; s[1][2] += a.y * bb.z; s[1][3] += a.y * bb.w;
            s[2][0] += a.z * bb.x; s[2][1] += a.z * bb.y; s[2][2] += a.z * bb.z; s[2][3] += a.z * bb.w;
            s[3][0] += a.w * bb.x; s[3][1] += a.w * bb.y; s[3][2] += a.w * bb.z; s[3][3] += a.w * bb.w;
        }

        // bias + online softmax (rows spread across 16 tx lanes of a half-warp)
        const int rg = r0 + ty * 4;
        const int cg = ct * 64 + tx * 4;
        float p[4][4];
#pragma unroll
        for (int i = 0; i < 4; ++i) {
            float4 aj = *reinterpret_cast<const float4*>(adj + (size_t)(rg + i) * N_ + cg);
            float v0 = s[i][0] * scale + aj.x + ((rg + i) == (cg + 0) ? 1.f : 0.f);
            float v1 = s[i][1] * scale + aj.y + ((rg + i) == (cg + 1) ? 1.f : 0.f);
            float v2 = s[i][2] * scale + aj.z + ((rg + i) == (cg + 2) ? 1.f : 0.f);
            float v3 = s[i][3] * scale + aj.w + ((rg + i) == (cg + 3) ? 1.f : 0.f);
            float tm = fmaxf(fmaxf(v0, v1), fmaxf(v2, v3));
            tm = fmaxf(tm, __shfl_xor_sync(0xffffffffu, tm, 1));
            tm = fmaxf(tm, __shfl_xor_sync(0xffffffffu, tm, 2));
            tm = fmaxf(tm, __shfl_xor_sync(0xffffffffu, tm, 4));
            tm = fmaxf(tm, __shfl_xor_sync(0xffffffffu, tm, 8));
            float mn = fmaxf(m_[i], tm);
            float alpha = exp2f((m_[i] - mn) * LOG2E);
            m_[i] = mn;
            p[i][0] = exp2f((v0 - mn) * LOG2E);
            p[i][1] = exp2f((v1 - mn) * LOG2E);
            p[i][2] = exp2f((v2 - mn) * LOG2E);
            p[i][3] = exp2f((v3 - mn) * LOG2E);
            float rs = p[i][0] + p[i][1] + p[i][2] + p[i][3];
            rs += __shfl_xor_sync(0xffffffffu, rs, 1);
            rs += __shfl_xor_sync(0xffffffffu, rs, 2);
            rs += __shfl_xor_sync(0xffffffffu, rs, 4);
            rs += __shfl_xor_sync(0xffffffffu, rs, 8);
            l_[i] = l_[i] * alpha + rs;
#pragma unroll
            for (int c = 0; c < 8; ++c) Oa[i][c] *= alpha;
        }

        __syncthreads();     // all S reads of Kt done before Pt overwrites it
        float* Pt = KtP;     // [64 kv][68] (padded, 16B-aligned rows)
#pragma unroll
        for (int j = 0; j < 4; ++j) {
            *reinterpret_cast<float4*>(Pt + (tx * 4 + j) * 68 + ty * 4) =
                make_float4(p[0][j], p[1][j], p[2][j], p[3][j]);
        }
        __syncthreads();

        // O += P V   (4 rows x 8 d-cols per thread)
        const float4* Vs4 = reinterpret_cast<const float4*>(Vs);
#pragma unroll 8
        for (int kk = 0; kk < 64; ++kk) {
            float4 pv = *reinterpret_cast<const float4*>(Pt + kk * 68 + ty * 4);
            float4 v0 = Vs4[kk * 32 + tx * 2];
            float4 v1 = Vs4[kk * 32 + tx * 2 + 1];
            Oa[0][0] += pv.x * v0.x; Oa[0][1] += pv.x * v0.y; Oa[0][2] += pv.x * v0.z; Oa[0][3] += pv.x * v0.w;
            Oa[0][4] += pv.x * v1.x; Oa[0][5] += pv.x * v1.y; Oa[0][6] += pv.x * v1.z; Oa[0][7] += pv.x * v1.w;
            Oa[1][0] += pv.y * v0.x; Oa[1][1] += pv.y * v0.y; Oa[1][2] += pv.y * v0.z; Oa[1][3] += pv.y * v0.w;
            Oa[1][4] += pv.y * v1.x; Oa[1][5] += pv.y * v1.y; Oa[1][6] += pv.y * v1.z; Oa[1][7] += pv.y * v1.w;
            Oa[2][0] += pv.z * v0.x; Oa[2][1] += pv.z * v0.y; Oa[2][2] += pv.z * v0.z; Oa[2][3] += pv.z * v0.w;
            Oa[2][4] += pv.z * v1.x; Oa[2][5] += pv.z * v1.y; Oa[2][6] += pv.z * v1.z; Oa[2][7] += pv.z * v1.w;
            Oa[3][0] += pv.w * v0.x; Oa[3][1] += pv.w * v0.y; Oa[3][2] += pv.w * v0.z; Oa[3][3] += pv.w * v0.w;
            Oa[3][4] += pv.w * v1.x; Oa[3][5] += pv.w * v1.y; Oa[3][6] += pv.w * v1.z; Oa[3][7] += pv.w * v1.w;
        }
    }

    // Epilogue: out = relu(O / l) + x
#pragma unroll
    for (int i = 0; i < 4; ++i) {
        float inv = 1.f / l_[i];
        int row = r0 + ty * 4 + i;
        const float4* xg = reinterpret_cast<const float4*>(X + ((size_t)b * N_ + row) * D_ + tx * 8);
        float4 x0 = xg[0], x1 = xg[1];
        float4 o0, o1;
        o0.x = fmaxf(Oa[i][0] * inv, 0.f) + x0.x;
        o0.y = fmaxf(Oa[i][1] * inv, 0.f) + x0.y;
        o0.z = fmaxf(Oa[i][2] * inv, 0.f) + x0.z;
        o0.w = fmaxf(Oa[i][3] * inv, 0.f) + x0.w;
        o1.x = fmaxf(Oa[i][4] * inv, 0.f) + x1.x;
        o1.y = fmaxf(Oa[i][5] * inv, 0.f) + x1.y;
        o1.z = fmaxf(Oa[i][6] * inv, 0.f) + x1.z;
        o1.w = fmaxf(Oa[i][7] * inv, 0.f) + x1.w;
        float4* og = reinterpret_cast<float4*>(Out + ((size_t)b * N_ + row) * D_ + tx * 8);
        og[0] = o0;
        og[1] = o1;
    }
}

// ---------------------------------------------------------------------------
extern "C" void kernel_launch(void* const* d_in, const int* in_sizes, int n_in,
                              void* d_out, int out_size)
{
    const float* x   = (const float*)d_in[0];
    const float* adj = (const float*)d_in[1];
    const float* Wq  = (const float*)d_in[2];
    const float* bq  = (const float*)d_in[3];
    const float* Wk  = (const float*)d_in[4];
    const float* bk  = (const float*)d_in[5];
    const float* Wv  = (const float*)d_in[6];
    const float* bv  = (const float*)d_in[7];
    const float* W1  = (const float*)d_in[8];
    const float* b1  = (const float*)d_in[9];
    const float* W2  = (const float*)d_in[10];
    const float* b2  = (const float*)d_in[11];
    float* out = (float*)d_out;

    float *q, *k, *v, *att, *h;
    cudaGetSymbolAddress((void**)&q,   g_q);
    cudaGetSymbolAddress((void**)&k,   g_k);
    cudaGetSymbolAddress((void**)&v,   g_v);
    cudaGetSymbolAddress((void**)&att, g_att);
    cudaGetSymbolAddress((void**)&h,   g_h);

    const int M = B_ * N_;                          // 16384
    const size_t gemm_smem = 2u * 128u * 128u * sizeof(float);   // 128 KB
    const size_t attn_smem = 24576u * sizeof(float);             // 96 KB
    cudaFuncSetAttribute(gemm128, cudaFuncAttributeMaxDynamicSharedMemorySize, (int)gemm_smem);
    cudaFuncSetAttribute(attn128, cudaFuncAttributeMaxDynamicSharedMemorySize, (int)attn_smem);

    // QKV projections
    gemm128<<<M / 128, 256, gemm_smem>>>(x, Wq, bq, nullptr, q, 0);
    gemm128<<<M / 128, 256, gemm_smem>>>(x, Wk, bk, nullptr, k, 0);
    gemm128<<<M / 128, 256, gemm_smem>>>(x, Wv, bv, nullptr, v, 0);

    // Fused attention + relu + residual
    dim3 ag(N_ / 64, B_);
    attn128<<<ag, 256, attn_smem>>>(q, k, v, adj, x, att);

    // FFN: h = relu(att @ W1^T + b1);  out = relu(h @ W2^T + b2) + att
    gemm128<<<M / 128, 256, gemm_smem>>>(att, W1, b1, nullptr, h, 1);
    gemm128<<<M / 128, 256, gemm_smem>>>(h, W2, b2, att, out, 1);
}

// round 5
// speedup vs baseline: 3.0106x; 3.0106x over previous
#include <cuda_runtime.h>
#include <cstdint>
#include <math.h>

#define B_ 4
#define N_ 4096
#define D_ 128

// ---------------- scratch (device globals; no runtime allocation) ----------
__device__ float g_q[B_ * N_ * D_];
__device__ float g_k[B_ * N_ * D_];
__device__ float g_v[B_ * N_ * D_];
__device__ float g_att[B_ * N_ * D_];
__device__ float g_h[B_ * N_ * D_];

// ======================= helpers ===========================================
__device__ __forceinline__ float cvt_tf32(float x) {
    uint32_t u;
    asm("cvt.rna.tf32.f32 %0, %1;" : "=r"(u) : "f"(x));
    return __uint_as_float(u);
}

__device__ __forceinline__ float ex2f(float x) {
    float r;
    asm("ex2.approx.ftz.f32 %0, %1;" : "=f"(r) : "f"(x));
    return r;
}

// D(16x8,f32) += A(16x8,tf32 row) * B(8x8,tf32 col)
__device__ __forceinline__ void mma_tf32(float* d,
                                         uint32_t a0, uint32_t a1, uint32_t a2, uint32_t a3,
                                         uint32_t b0, uint32_t b1) {
    asm volatile(
        "mma.sync.aligned.m16n8k8.row.col.f32.tf32.tf32.f32 "
        "{%0,%1,%2,%3}, {%4,%5,%6,%7}, {%8,%9}, {%0,%1,%2,%3};"
        : "+f"(d[0]), "+f"(d[1]), "+f"(d[2]), "+f"(d[3])
        : "r"(a0), "r"(a1), "r"(a2), "r"(a3), "r"(b0), "r"(b1));
}

__device__ __forceinline__ uint32_t fbits(float x) { return __float_as_uint(x); }

// ---------------------------------------------------------------------------
// Flash attention via mma.sync tf32, fixed-shift softmax (C=12):
//   S = Q K^T ; P = exp(S*scale + adj + eye - C) ; l += rowsum(P) ; O += P V
//   out = relu(O/l) + x
// 512 threads = 16 warps: w_m = wid&7 (16 q-rows), w_n = wid>>3 (64-col slice)
// Smem: Qs[128][132], KP[128][132] (K tile then P tile), Vs[128][136]
// ---------------------------------------------------------------------------
#define QS_STRIDE 132
#define VS_STRIDE 136

__global__ __launch_bounds__(512, 1) void attn_mma(
    const float* __restrict__ Q, const float* __restrict__ K,
    const float* __restrict__ V, const float* __restrict__ adj,
    const float* __restrict__ X, float* __restrict__ Out)
{
    extern __shared__ float sm[];
    float* Qs = sm;                       // 128*132 = 16896
    float* KP = sm + 16896;               // 128*132
    float* Vs = sm + 33792;               // 128*136 = 17408
    __shared__ float l_part[2][128];

    const int tid  = threadIdx.x;
    const int wid  = tid >> 5;
    const int lane = tid & 31;
    const int w_m  = wid & 7;
    const int w_n  = wid >> 3;
    const int gq   = lane >> 2;    // groupID (row within fragment)
    const int tq   = lane & 3;     // threadID_in_group (col within fragment)
    const int b    = blockIdx.y;
    const int q0   = blockIdx.x * 128;

    // ---- stage Q (tf32-rounded) ----
    {
        const float4* Qg = reinterpret_cast<const float4*>(Q + ((size_t)b * N_ + q0) * D_);
#pragma unroll
        for (int it = 0; it < 8; ++it) {
            int idx = tid + it * 512;          // 4096 float4
            int r = idx >> 5, c4 = idx & 31;
            float4 v4 = Qg[idx];
            v4.x = cvt_tf32(v4.x); v4.y = cvt_tf32(v4.y);
            v4.z = cvt_tf32(v4.z); v4.w = cvt_tf32(v4.w);
            *reinterpret_cast<float4*>(Qs + r * QS_STRIDE + c4 * 4) = v4;
        }
    }

    // fragment base pointers (bank-conflict-free by construction)
    const float* qa = Qs + (w_m * 16 + gq) * QS_STRIDE + tq;             // MMA1 A
    const float* kb = KP + (w_n * 64 + gq) * QS_STRIDE + tq;             // MMA1 B
    const float* pa = KP + (w_m * 16 + gq) * QS_STRIDE + tq;             // MMA2 A
    const float* vb = Vs + tq * VS_STRIDE + (w_n * 64 + gq);             // MMA2 B

    const int trow0 = q0 + w_m * 16 + gq;
    const int trow1 = trow0 + 8;
    const float scaleL = 0.088388347648318447f * 1.4426950408889634f;   // scale*log2e
    const float LOG2E  = 1.4426950408889634f;
    const float C      = 12.0f;

    float lsum0 = 0.f, lsum1 = 0.f;
    float Oacc[8][4];
#pragma unroll
    for (int nt = 0; nt < 8; ++nt)
#pragma unroll
        for (int j = 0; j < 4; ++j) Oacc[nt][j] = 0.f;

    for (int ct = 0; ct < N_ / 128; ++ct) {
        __syncthreads();   // prev MMA2 done reading KP/Vs
        // ---- stage K (tf32), V (tf32) ----
        {
            const float4* Kg = reinterpret_cast<const float4*>(K + ((size_t)b * N_ + ct * 128) * D_);
            const float4* Vg = reinterpret_cast<const float4*>(V + ((size_t)b * N_ + ct * 128) * D_);
#pragma unroll
            for (int it = 0; it < 8; ++it) {
                int idx = tid + it * 512;
                int r = idx >> 5, c4 = idx & 31;
                float4 k4 = Kg[idx];
                k4.x = cvt_tf32(k4.x); k4.y = cvt_tf32(k4.y);
                k4.z = cvt_tf32(k4.z); k4.w = cvt_tf32(k4.w);
                *reinterpret_cast<float4*>(KP + r * QS_STRIDE + c4 * 4) = k4;
                float4 v4 = Vg[idx];
                v4.x = cvt_tf32(v4.x); v4.y = cvt_tf32(v4.y);
                v4.z = cvt_tf32(v4.z); v4.w = cvt_tf32(v4.w);
                *reinterpret_cast<float4*>(Vs + r * VS_STRIDE + c4 * 4) = v4;
            }
        }
        __syncthreads();

        // ---- MMA1: S = Q @ K^T  (warp tile 16 x 64) ----
        float Sacc[8][4];
#pragma unroll
        for (int nt = 0; nt < 8; ++nt)
#pragma unroll
            for (int j = 0; j < 4; ++j) Sacc[nt][j] = 0.f;

#pragma unroll
        for (int ks = 0; ks < 16; ++ks) {
            uint32_t a0 = fbits(qa[ks * 8]);
            uint32_t a1 = fbits(qa[8 * QS_STRIDE + ks * 8]);
            uint32_t a2 = fbits(qa[ks * 8 + 4]);
            uint32_t a3 = fbits(qa[8 * QS_STRIDE + ks * 8 + 4]);
#pragma unroll
            for (int nt = 0; nt < 8; ++nt) {
                uint32_t b0 = fbits(kb[nt * 8 * QS_STRIDE + ks * 8]);
                uint32_t b1 = fbits(kb[nt * 8 * QS_STRIDE + ks * 8 + 4]);
                mma_tf32(Sacc[nt], a0, a1, a2, a3, b0, b1);
            }
        }

        // ---- softmax (fixed shift) in registers ----
        float pr[8][4];
#pragma unroll
        for (int nt = 0; nt < 8; ++nt) {
            int colg = ct * 128 + w_n * 64 + nt * 8 + 2 * tq;
            float2 aj0 = *reinterpret_cast<const float2*>(adj + (size_t)trow0 * N_ + colg);
            float2 aj1 = *reinterpret_cast<const float2*>(adj + (size_t)trow1 * N_ + colg);
            float p0 = ex2f(fmaf(Sacc[nt][0], scaleL,
                                 (aj0.x + ((trow0 == colg)     ? 1.f : 0.f) - C) * LOG2E));
            float p1 = ex2f(fmaf(Sacc[nt][1], scaleL,
                                 (aj0.y + ((trow0 == colg + 1) ? 1.f : 0.f) - C) * LOG2E));
            float p2 = ex2f(fmaf(Sacc[nt][2], scaleL,
                                 (aj1.x + ((trow1 == colg)     ? 1.f : 0.f) - C) * LOG2E));
            float p3 = ex2f(fmaf(Sacc[nt][3], scaleL,
                                 (aj1.y + ((trow1 == colg + 1) ? 1.f : 0.f) - C) * LOG2E));
            lsum0 += p0 + p1;
            lsum1 += p2 + p3;
            pr[nt][0] = cvt_tf32(p0); pr[nt][1] = cvt_tf32(p1);
            pr[nt][2] = cvt_tf32(p2); pr[nt][3] = cvt_tf32(p3);
        }

        __syncthreads();   // all MMA1 reads of K done before P overwrites KP

        // ---- store P into KP (row = local q, col = local kv) ----
        {
            const int rl0 = w_m * 16 + gq;
            const int cl  = w_n * 64 + 2 * tq;
#pragma unroll
            for (int nt = 0; nt < 8; ++nt) {
                *reinterpret_cast<float2*>(KP + rl0 * QS_STRIDE + cl + nt * 8) =
                    make_float2(pr[nt][0], pr[nt][1]);
                *reinterpret_cast<float2*>(KP + (rl0 + 8) * QS_STRIDE + cl + nt * 8) =
                    make_float2(pr[nt][2], pr[nt][3]);
            }
        }
        __syncthreads();

        // ---- MMA2: O += P @ V  (warp tile 16 q x 64 d) ----
#pragma unroll
        for (int ks = 0; ks < 16; ++ks) {
            uint32_t a0 = fbits(pa[ks * 8]);
            uint32_t a1 = fbits(pa[8 * QS_STRIDE + ks * 8]);
            uint32_t a2 = fbits(pa[ks * 8 + 4]);
            uint32_t a3 = fbits(pa[8 * QS_STRIDE + ks * 8 + 4]);
#pragma unroll
            for (int nt = 0; nt < 8; ++nt) {
                uint32_t b0 = fbits(vb[ks * 8 * VS_STRIDE + nt * 8]);
                uint32_t b1 = fbits(vb[ks * 8 * VS_STRIDE + 4 * VS_STRIDE + nt * 8]);
                mma_tf32(Oacc[nt], a0, a1, a2, a3, b0, b1);
            }
        }
    }

    // ---- epilogue: reduce l, out = relu(O/l) + x ----
    lsum0 += __shfl_xor_sync(0xffffffffu, lsum0, 1);
    lsum0 += __shfl_xor_sync(0xffffffffu, lsum0, 2);
    lsum1 += __shfl_xor_sync(0xffffffffu, lsum1, 1);
    lsum1 += __shfl_xor_sync(0xffffffffu, lsum1, 2);
    if (tq == 0) {
        l_part[w_n][w_m * 16 + gq]     = lsum0;
        l_part[w_n][w_m * 16 + gq + 8] = lsum1;
    }
    __syncthreads();

    const int rl0 = w_m * 16 + gq;
    const int rl1 = rl0 + 8;
    const float linv0 = 1.f / (l_part[0][rl0] + l_part[1][rl0]);
    const float linv1 = 1.f / (l_part[0][rl1] + l_part[1][rl1]);

#pragma unroll
    for (int nt = 0; nt < 8; ++nt) {
        int cl = w_n * 64 + nt * 8 + 2 * tq;
        size_t base0 = ((size_t)b * N_ + q0 + rl0) * D_ + cl;
        size_t base1 = ((size_t)b * N_ + q0 + rl1) * D_ + cl;
        float2 x0 = *reinterpret_cast<const float2*>(X + base0);
        float2 x1 = *reinterpret_cast<const float2*>(X + base1);
        float2 o0, o1;
        o0.x = fmaxf(Oacc[nt][0] * linv0, 0.f) + x0.x;
        o0.y = fmaxf(Oacc[nt][1] * linv0, 0.f) + x0.y;
        o1.x = fmaxf(Oacc[nt][2] * linv1, 0.f) + x1.x;
        o1.y = fmaxf(Oacc[nt][3] * linv1, 0.f) + x1.y;
        *reinterpret_cast<float2*>(Out + base0) = o0;
        *reinterpret_cast<float2*>(Out + base1) = o1;
    }
}

// ---------------------------------------------------------------------------
// Generic GEMM: Y[M,128] = act(X[M,128] @ W^T[128,128] + b) (+ resid)
// (unchanged from R1 — validated, fp32 exact)
// ---------------------------------------------------------------------------
__global__ __launch_bounds__(256) void gemm128(
    const float* __restrict__ X, const float* __restrict__ W,
    const float* __restrict__ bias, const float* __restrict__ resid,
    float* __restrict__ Y, int do_relu)
{
    extern __shared__ float sm[];
    float* Xs = sm;
    float* Wt = sm + 128 * 128;

    const int tid = threadIdx.x;
    const int ty = tid >> 4;
    const int tx = tid & 15;
    const int row0 = blockIdx.x * 128;

    {
        const float4* Xg = reinterpret_cast<const float4*>(X + (size_t)row0 * D_);
        float4* Xs4 = reinterpret_cast<float4*>(Xs);
#pragma unroll
        for (int it = 0; it < 16; ++it) {
            int idx = tid + it * 256;
            Xs4[idx] = Xg[idx];
        }
    }
    {
        const float4* Wg = reinterpret_cast<const float4*>(W);
#pragma unroll
        for (int it = 0; it < 16; ++it) {
            int idx = tid + it * 256;
            int j  = idx & 127;
            int kq = idx >> 7;
            float4 w = Wg[(size_t)j * 32 + kq];
            Wt[(kq * 4 + 0) * 128 + j] = w.x;
            Wt[(kq * 4 + 1) * 128 + j] = w.y;
            Wt[(kq * 4 + 2) * 128 + j] = w.z;
            Wt[(kq * 4 + 3) * 128 + j] = w.w;
        }
    }
    __syncthreads();

    float acc[8][8];
#pragma unroll
    for (int i = 0; i < 8; ++i)
#pragma unroll
        for (int j = 0; j < 8; ++j) acc[i][j] = 0.f;

    const float4* Xs4 = reinterpret_cast<const float4*>(Xs);
    const float4* Wt4 = reinterpret_cast<const float4*>(Wt);

    for (int kq = 0; kq < 32; ++kq) {
        float4 xa[8];
#pragma unroll
        for (int i = 0; i < 8; ++i) xa[i] = Xs4[(ty * 8 + i) * 32 + kq];
#pragma unroll
        for (int kk = 0; kk < 4; ++kk) {
            int k = kq * 4 + kk;
            float4 w0 = Wt4[k * 32 + tx * 2];
            float4 w1 = Wt4[k * 32 + tx * 2 + 1];
#pragma unroll
            for (int i = 0; i < 8; ++i) {
                float a = reinterpret_cast<const float*>(&xa[i])[kk];
                acc[i][0] += a * w0.x; acc[i][1] += a * w0.y;
                acc[i][2] += a * w0.z; acc[i][3] += a * w0.w;
                acc[i][4] += a * w1.x; acc[i][5] += a * w1.y;
                acc[i][6] += a * w1.z; acc[i][7] += a * w1.w;
            }
        }
    }

    float bb[8];
    {
        float4 b0 = *reinterpret_cast<const float4*>(bias + tx * 8);
        float4 b1 = *reinterpret_cast<const float4*>(bias + tx * 8 + 4);
        bb[0] = b0.x; bb[1] = b0.y; bb[2] = b0.z; bb[3] = b0.w;
        bb[4] = b1.x; bb[5] = b1.y; bb[6] = b1.z; bb[7] = b1.w;
    }
#pragma unroll
    for (int i = 0; i < 8; ++i) {
        int row = row0 + ty * 8 + i;
        float v[8];
#pragma unroll
        for (int j = 0; j < 8; ++j) {
            float val = acc[i][j] + bb[j];
            if (do_relu) val = fmaxf(val, 0.f);
            v[j] = val;
        }
        if (resid) {
            const float4* rg = reinterpret_cast<const float4*>(resid + (size_t)row * D_ + tx * 8);
            float4 r0 = rg[0], r1 = rg[1];
            v[0] += r0.x; v[1] += r0.y; v[2] += r0.z; v[3] += r0.w;
            v[4] += r1.x; v[5] += r1.y; v[6] += r1.z; v[7] += r1.w;
        }
        float4* yg = reinterpret_cast<float4*>(Y + (size_t)row * D_ + tx * 8);
        yg[0] = make_float4(v[0], v[1], v[2], v[3]);
        yg[1] = make_float4(v[4], v[5], v[6], v[7]);
    }
}

// ---------------------------------------------------------------------------
extern "C" void kernel_launch(void* const* d_in, const int* in_sizes, int n_in,
                              void* d_out, int out_size)
{
    const float* x   = (const float*)d_in[0];
    const float* adj = (const float*)d_in[1];
    const float* Wq  = (const float*)d_in[2];
    const float* bq  = (const float*)d_in[3];
    const float* Wk  = (const float*)d_in[4];
    const float* bk  = (const float*)d_in[5];
    const float* Wv  = (const float*)d_in[6];
    const float* bv  = (const float*)d_in[7];
    const float* W1  = (const float*)d_in[8];
    const float* b1  = (const float*)d_in[9];
    const float* W2  = (const float*)d_in[10];
    const float* b2  = (const float*)d_in[11];
    float* out = (float*)d_out;

    float *q, *k, *v, *att, *hbuf;
    cudaGetSymbolAddress((void**)&q,    g_q);
    cudaGetSymbolAddress((void**)&k,    g_k);
    cudaGetSymbolAddress((void**)&v,    g_v);
    cudaGetSymbolAddress((void**)&att,  g_att);
    cudaGetSymbolAddress((void**)&hbuf, g_h);

    const int M = B_ * N_;
    const size_t gemm_smem = 2u * 128u * 128u * sizeof(float);  // 128 KB
    const size_t attn_smem = (16896u + 16896u + 17408u) * sizeof(float);  // 200 KB
    cudaFuncSetAttribute(gemm128, cudaFuncAttributeMaxDynamicSharedMemorySize, (int)gemm_smem);
    cudaFuncSetAttribute(attn_mma, cudaFuncAttributeMaxDynamicSharedMemorySize, (int)attn_smem);

    gemm128<<<M / 128, 256, gemm_smem>>>(x, Wq, bq, nullptr, q, 0);
    gemm128<<<M / 128, 256, gemm_smem>>>(x, Wk, bk, nullptr, k, 0);
    gemm128<<<M / 128, 256, gemm_smem>>>(x, Wv, bv, nullptr, v, 0);

    dim3 ag(N_ / 128, B_);
    attn_mma<<<ag, 512, attn_smem>>>(q, k, v, adj, x, att);

    gemm128<<<M / 128, 256, gemm_smem>>>(att, W1, b1, nullptr, hbuf, 1);
    gemm128<<<M / 128, 256, gemm_smem>>>(hbuf, W2, b2, att, out, 1);
}

// round 6
// speedup vs baseline: 4.9290x; 1.6372x over previous
#include <cuda_runtime.h>
#include <cuda_fp16.h>
#include <cstdint>
#include <math.h>

#define B_ 4
#define N_ 4096
#define D_ 128
#define HS 136   // halves per smem row (272B stride: conflict-free ldmatrix)

// ---------------- scratch (device globals; no runtime allocation) ----------
__device__ float g_q[B_ * N_ * D_];
__device__ float g_k[B_ * N_ * D_];
__device__ float g_v[B_ * N_ * D_];
__device__ float g_att[B_ * N_ * D_];
__device__ float g_h[B_ * N_ * D_];

// ======================= helpers ===========================================
__device__ __forceinline__ uint32_t smem_u32(const void* p) {
    uint32_t a;
    asm("{ .reg .u64 t; cvta.to.shared.u64 t, %1; cvt.u32.u64 %0, t; }"
        : "=r"(a) : "l"(p));
    return a;
}

__device__ __forceinline__ float ex2f(float x) {
    float r;
    asm("ex2.approx.ftz.f32 %0, %1;" : "=f"(r) : "f"(x));
    return r;
}

__device__ __forceinline__ uint32_t f2h2(float a, float b) {
    __half2 h = __floats2half2_rn(a, b);
    return *reinterpret_cast<uint32_t*>(&h);
}

__device__ __forceinline__ void sts64(uint32_t addr, uint32_t lo, uint32_t hi) {
    asm volatile("st.shared.v2.b32 [%0], {%1,%2};" :: "r"(addr), "r"(lo), "r"(hi) : "memory");
}
__device__ __forceinline__ void sts32u(uint32_t addr, uint32_t v) {
    asm volatile("st.shared.b32 [%0], %1;" :: "r"(addr), "r"(v) : "memory");
}

__device__ __forceinline__ void ldsm_x4(uint32_t& r0, uint32_t& r1, uint32_t& r2, uint32_t& r3,
                                        uint32_t addr) {
    asm volatile("ldmatrix.sync.aligned.m8n8.x4.shared.b16 {%0,%1,%2,%3}, [%4];"
        : "=r"(r0), "=r"(r1), "=r"(r2), "=r"(r3) : "r"(addr));
}
__device__ __forceinline__ void ldsm_x4_t(uint32_t& r0, uint32_t& r1, uint32_t& r2, uint32_t& r3,
                                          uint32_t addr) {
    asm volatile("ldmatrix.sync.aligned.m8n8.x4.trans.shared.b16 {%0,%1,%2,%3}, [%4];"
        : "=r"(r0), "=r"(r1), "=r"(r2), "=r"(r3) : "r"(addr));
}

// D(16x8,f32) += A(16x16,f16 row) * B(16x8,f16 col)
__device__ __forceinline__ void mma_f16(float* d,
                                        uint32_t a0, uint32_t a1, uint32_t a2, uint32_t a3,
                                        uint32_t b0, uint32_t b1) {
    asm volatile(
        "mma.sync.aligned.m16n8k16.row.col.f32.f16.f16.f32 "
        "{%0,%1,%2,%3}, {%4,%5,%6,%7}, {%8,%9}, {%0,%1,%2,%3};"
        : "+f"(d[0]), "+f"(d[1]), "+f"(d[2]), "+f"(d[3])
        : "r"(a0), "r"(a1), "r"(a2), "r"(a3), "r"(b0), "r"(b1));
}

// ---------------------------------------------------------------------------
// fp16 flash attention, fixed-shift softmax (C=3):
//   S = Q K^T ; P = exp(S*scale + adj + eye - C) ; l += rowsum(P) ; O += P V
//   out = relu(O/l) + x
// 512 thr = 16 warps, 4x4 grid: w_m = wid&3 (32 q-rows), w_n = wid>>2 (32 cols)
// Smem: Qh[128][HS], KPh[128][HS] (K then P), Vh[128][HS]  (halves)
// ---------------------------------------------------------------------------
__global__ __launch_bounds__(512, 1) void attn_f16(
    const float* __restrict__ Q, const float* __restrict__ K,
    const float* __restrict__ V, const float* __restrict__ adj,
    const float* __restrict__ X, float* __restrict__ Out)
{
    extern __shared__ __align__(16) char smraw[];
    const uint32_t Qb = smem_u32(smraw);
    const uint32_t Kb = Qb + 128u * HS * 2u;   // K tile, later P tile
    const uint32_t Vb = Kb + 128u * HS * 2u;
    __shared__ float l_part[4][128];

    const int tid  = threadIdx.x;
    const int wid  = tid >> 5;
    const int lane = tid & 31;
    const int w_m  = wid & 3;      // q-row group: 32 rows
    const int w_n  = wid >> 2;     // col group:   32 cols
    const int gq   = lane >> 2;
    const int tq   = lane & 3;
    const int lr   = lane & 7;
    const int g8   = lane >> 3;
    const int b    = blockIdx.y;
    const int q0   = blockIdx.x * 128;

    // ldmatrix per-lane address components
    const int arow = lr + ((g8 & 1) ? 8 : 0);   // A-type (Q/P): rows m, cols k
    const int acol = (g8 & 2) ? 8 : 0;
    const int brow = lr + ((g8 & 2) ? 8 : 0);   // B-type (K):   rows n, cols k
    const int bcol = (g8 & 1) ? 8 : 0;
    const int vrow = lr + ((g8 & 1) ? 8 : 0);   // B-trans (V):  rows kv, cols d
    const int vcol = (g8 & 2) ? 8 : 0;

    // ---- stage Q (fp16) ----
    {
        const float4* Qg = reinterpret_cast<const float4*>(Q + ((size_t)b * N_ + q0) * D_);
#pragma unroll
        for (int it = 0; it < 8; ++it) {
            int idx = tid + it * 512;          // 4096 float4 = 128 x 32
            int r = idx >> 5, c4 = idx & 31;
            float4 v4 = Qg[idx];
            sts64(Qb + (uint32_t)(r * HS + c4 * 4) * 2u,
                  f2h2(v4.x, v4.y), f2h2(v4.z, v4.w));
        }
    }

    const float scaleL = 0.088388347648318447f * 1.4426950408889634f;  // scale*log2e
    const float LOG2E  = 1.4426950408889634f;
    const float C      = 3.0f;

    float lsum[4];
    float Oacc[2][4][4];
#pragma unroll
    for (int i = 0; i < 4; ++i) lsum[i] = 0.f;
#pragma unroll
    for (int mi = 0; mi < 2; ++mi)
#pragma unroll
        for (int nt = 0; nt < 4; ++nt)
#pragma unroll
            for (int j = 0; j < 4; ++j) Oacc[mi][nt][j] = 0.f;

    for (int ct = 0; ct < N_ / 128; ++ct) {
        __syncthreads();   // prev iter's MMA2 reads of KPh/Vh complete
        // ---- stage K, V (fp16) ----
        {
            const float4* Kg = reinterpret_cast<const float4*>(K + ((size_t)b * N_ + ct * 128) * D_);
            const float4* Vg = reinterpret_cast<const float4*>(V + ((size_t)b * N_ + ct * 128) * D_);
#pragma unroll
            for (int it = 0; it < 8; ++it) {
                int idx = tid + it * 512;
                int r = idx >> 5, c4 = idx & 31;
                uint32_t off = (uint32_t)(r * HS + c4 * 4) * 2u;
                float4 k4 = Kg[idx];
                sts64(Kb + off, f2h2(k4.x, k4.y), f2h2(k4.z, k4.w));
                float4 v4 = Vg[idx];
                sts64(Vb + off, f2h2(v4.x, v4.y), f2h2(v4.z, v4.w));
            }
        }
        __syncthreads();

        // ---- MMA1: S = Q @ K^T  (warp tile 32x32, 8 k16-steps) ----
        float Sacc[2][4][4];
#pragma unroll
        for (int mi = 0; mi < 2; ++mi)
#pragma unroll
            for (int nt = 0; nt < 4; ++nt)
#pragma unroll
                for (int j = 0; j < 4; ++j) Sacc[mi][nt][j] = 0.f;

#pragma unroll
        for (int ks = 0; ks < 8; ++ks) {
            uint32_t qa[2][4];
#pragma unroll
            for (int mi = 0; mi < 2; ++mi)
                ldsm_x4(qa[mi][0], qa[mi][1], qa[mi][2], qa[mi][3],
                        Qb + (uint32_t)((w_m * 32 + mi * 16 + arow) * HS + ks * 16 + acol) * 2u);
#pragma unroll
            for (int np = 0; np < 2; ++np) {
                uint32_t r0, r1, r2, r3;
                ldsm_x4(r0, r1, r2, r3,
                        Kb + (uint32_t)((w_n * 32 + np * 16 + brow) * HS + ks * 16 + bcol) * 2u);
#pragma unroll
                for (int mi = 0; mi < 2; ++mi) {
                    mma_f16(Sacc[mi][np * 2],     qa[mi][0], qa[mi][1], qa[mi][2], qa[mi][3], r0, r1);
                    mma_f16(Sacc[mi][np * 2 + 1], qa[mi][0], qa[mi][1], qa[mi][2], qa[mi][3], r2, r3);
                }
            }
        }

        // ---- softmax (fixed shift) ----
        uint32_t ph[2][4][2];
#pragma unroll
        for (int mi = 0; mi < 2; ++mi) {
            const int tr0 = q0 + w_m * 32 + mi * 16 + gq;
            const int tr1 = tr0 + 8;
#pragma unroll
            for (int nt = 0; nt < 4; ++nt) {
                int cg = ct * 128 + w_n * 32 + nt * 8 + 2 * tq;
                float2 aj0 = *reinterpret_cast<const float2*>(adj + (size_t)tr0 * N_ + cg);
                float2 aj1 = *reinterpret_cast<const float2*>(adj + (size_t)tr1 * N_ + cg);
                float p0 = ex2f(fmaf(Sacc[mi][nt][0], scaleL,
                                     (aj0.x + ((tr0 == cg)     ? 1.f : 0.f) - C) * LOG2E));
                float p1 = ex2f(fmaf(Sacc[mi][nt][1], scaleL,
                                     (aj0.y + ((tr0 == cg + 1) ? 1.f : 0.f) - C) * LOG2E));
                float p2 = ex2f(fmaf(Sacc[mi][nt][2], scaleL,
                                     (aj1.x + ((tr1 == cg)     ? 1.f : 0.f) - C) * LOG2E));
                float p3 = ex2f(fmaf(Sacc[mi][nt][3], scaleL,
                                     (aj1.y + ((tr1 == cg + 1) ? 1.f : 0.f) - C) * LOG2E));
                lsum[mi * 2 + 0] += p0 + p1;
                lsum[mi * 2 + 1] += p2 + p3;
                ph[mi][nt][0] = f2h2(p0, p1);
                ph[mi][nt][1] = f2h2(p2, p3);
            }
        }

        __syncthreads();   // all MMA1 reads of K done before P overwrites KPh

        // ---- store P (fp16) into KPh ----
        {
            const int rl = w_m * 32 + gq;
            const int cl = w_n * 32 + 2 * tq;
#pragma unroll
            for (int mi = 0; mi < 2; ++mi)
#pragma unroll
                for (int nt = 0; nt < 4; ++nt) {
                    sts32u(Kb + (uint32_t)((rl + mi * 16)     * HS + cl + nt * 8) * 2u, ph[mi][nt][0]);
                    sts32u(Kb + (uint32_t)((rl + mi * 16 + 8) * HS + cl + nt * 8) * 2u, ph[mi][nt][1]);
                }
        }
        __syncthreads();

        // ---- MMA2: O += P @ V  (V via trans ldmatrix; warp tile 32 q x 32 d) ----
#pragma unroll
        for (int ks = 0; ks < 8; ++ks) {
            uint32_t pa[2][4];
#pragma unroll
            for (int mi = 0; mi < 2; ++mi)
                ldsm_x4(pa[mi][0], pa[mi][1], pa[mi][2], pa[mi][3],
                        Kb + (uint32_t)((w_m * 32 + mi * 16 + arow) * HS + ks * 16 + acol) * 2u);
#pragma unroll
            for (int np = 0; np < 2; ++np) {
                uint32_t r0, r1, r2, r3;
                ldsm_x4_t(r0, r1, r2, r3,
                          Vb + (uint32_t)((ks * 16 + vrow) * HS + w_n * 32 + np * 16 + vcol) * 2u);
#pragma unroll
                for (int mi = 0; mi < 2; ++mi) {
                    mma_f16(Oacc[mi][np * 2],     pa[mi][0], pa[mi][1], pa[mi][2], pa[mi][3], r0, r1);
                    mma_f16(Oacc[mi][np * 2 + 1], pa[mi][0], pa[mi][1], pa[mi][2], pa[mi][3], r2, r3);
                }
            }
        }
    }

    // ---- epilogue: reduce l across tq lanes and the 4 w_n warps ----
#pragma unroll
    for (int li = 0; li < 4; ++li) {
        lsum[li] += __shfl_xor_sync(0xffffffffu, lsum[li], 1);
        lsum[li] += __shfl_xor_sync(0xffffffffu, lsum[li], 2);
    }
    if (tq == 0) {
#pragma unroll
        for (int mi = 0; mi < 2; ++mi)
#pragma unroll
            for (int hi = 0; hi < 2; ++hi)
                l_part[w_n][w_m * 32 + mi * 16 + hi * 8 + gq] = lsum[mi * 2 + hi];
    }
    __syncthreads();

#pragma unroll
    for (int mi = 0; mi < 2; ++mi)
#pragma unroll
        for (int hi = 0; hi < 2; ++hi) {
            const int rl = w_m * 32 + mi * 16 + hi * 8 + gq;
            const float linv = 1.f / (l_part[0][rl] + l_part[1][rl] +
                                      l_part[2][rl] + l_part[3][rl]);
#pragma unroll
            for (int nt = 0; nt < 4; ++nt) {
                int cl = w_n * 32 + nt * 8 + 2 * tq;
                size_t base = ((size_t)b * N_ + q0 + rl) * D_ + cl;
                float2 x2 = *reinterpret_cast<const float2*>(X + base);
                float2 o;
                o.x = fmaxf(Oacc[mi][nt][hi * 2]     * linv, 0.f) + x2.x;
                o.y = fmaxf(Oacc[mi][nt][hi * 2 + 1] * linv, 0.f) + x2.y;
                *reinterpret_cast<float2*>(Out + base) = o;
            }
        }
}

// ---------------------------------------------------------------------------
// Generic GEMM: Y[M,128] = act(X[M,128] @ W^T[128,128] + b) (+ resid)
// (unchanged — validated, fp32 exact)
// ---------------------------------------------------------------------------
__global__ __launch_bounds__(256) void gemm128(
    const float* __restrict__ X, const float* __restrict__ W,
    const float* __restrict__ bias, const float* __restrict__ resid,
    float* __restrict__ Y, int do_relu)
{
    extern __shared__ float sm[];
    float* Xs = sm;
    float* Wt = sm + 128 * 128;

    const int tid = threadIdx.x;
    const int ty = tid >> 4;
    const int tx = tid & 15;
    const int row0 = blockIdx.x * 128;

    {
        const float4* Xg = reinterpret_cast<const float4*>(X + (size_t)row0 * D_);
        float4* Xs4 = reinterpret_cast<float4*>(Xs);
#pragma unroll
        for (int it = 0; it < 16; ++it) {
            int idx = tid + it * 256;
            Xs4[idx] = Xg[idx];
        }
    }
    {
        const float4* Wg = reinterpret_cast<const float4*>(W);
#pragma unroll
        for (int it = 0; it < 16; ++it) {
            int idx = tid + it * 256;
            int j  = idx & 127;
            int kq = idx >> 7;
            float4 w = Wg[(size_t)j * 32 + kq];
            Wt[(kq * 4 + 0) * 128 + j] = w.x;
            Wt[(kq * 4 + 1) * 128 + j] = w.y;
            Wt[(kq * 4 + 2) * 128 + j] = w.z;
            Wt[(kq * 4 + 3) * 128 + j] = w.w;
        }
    }
    __syncthreads();

    float acc[8][8];
#pragma unroll
    for (int i = 0; i < 8; ++i)
#pragma unroll
        for (int j = 0; j < 8; ++j) acc[i][j] = 0.f;

    const float4* Xs4 = reinterpret_cast<const float4*>(Xs);
    const float4* Wt4 = reinterpret_cast<const float4*>(Wt);

    for (int kq = 0; kq < 32; ++kq) {
        float4 xa[8];
#pragma unroll
        for (int i = 0; i < 8; ++i) xa[i] = Xs4[(ty * 8 + i) * 32 + kq];
#pragma unroll
        for (int kk = 0; kk < 4; ++kk) {
            int k = kq * 4 + kk;
            float4 w0 = Wt4[k * 32 + tx * 2];
            float4 w1 = Wt4[k * 32 + tx * 2 + 1];
#pragma unroll
            for (int i = 0; i < 8; ++i) {
                float a = reinterpret_cast<const float*>(&xa[i])[kk];
                acc[i][0] += a * w0.x; acc[i][1] += a * w0.y;
                acc[i][2] += a * w0.z; acc[i][3] += a * w0.w;
                acc[i][4] += a * w1.x; acc[i][5] += a * w1.y;
                acc[i][6] += a * w1.z; acc[i][7] += a * w1.w;
            }
        }
    }

    float bb[8];
    {
        float4 b0 = *reinterpret_cast<const float4*>(bias + tx * 8);
        float4 b1 = *reinterpret_cast<const float4*>(bias + tx * 8 + 4);
        bb[0] = b0.x; bb[1] = b0.y; bb[2] = b0.z; bb[3] = b0.w;
        bb[4] = b1.x; bb[5] = b1.y; bb[6] = b1.z; bb[7] = b1.w;
    }
#pragma unroll
    for (int i = 0; i < 8; ++i) {
        int row = row0 + ty * 8 + i;
        float v[8];
#pragma unroll
        for (int j = 0; j < 8; ++j) {
            float val = acc[i][j] + bb[j];
            if (do_relu) val = fmaxf(val, 0.f);
            v[j] = val;
        }
        if (resid) {
            const float4* rg = reinterpret_cast<const float4*>(resid + (size_t)row * D_ + tx * 8);
            float4 r0 = rg[0], r1 = rg[1];
            v[0] += r0.x; v[1] += r0.y; v[2] += r0.z; v[3] += r0.w;
            v[4] += r1.x; v[5] += r1.y; v[6] += r1.z; v[7] += r1.w;
        }
        float4* yg = reinterpret_cast<float4*>(Y + (size_t)row * D_ + tx * 8);
        yg[0] = make_float4(v[0], v[1], v[2], v[3]);
        yg[1] = make_float4(v[4], v[5], v[6], v[7]);
    }
}

// ---------------------------------------------------------------------------
extern "C" void kernel_launch(void* const* d_in, const int* in_sizes, int n_in,
                              void* d_out, int out_size)
{
    const float* x   = (const float*)d_in[0];
    const float* adj = (const float*)d_in[1];
    const float* Wq  = (const float*)d_in[2];
    const float* bq  = (const float*)d_in[3];
    const float* Wk  = (const float*)d_in[4];
    const float* bk  = (const float*)d_in[5];
    const float* Wv  = (const float*)d_in[6];
    const float* bv  = (const float*)d_in[7];
    const float* W1  = (const float*)d_in[8];
    const float* b1  = (const float*)d_in[9];
    const float* W2  = (const float*)d_in[10];
    const float* b2  = (const float*)d_in[11];
    float* out = (float*)d_out;

    float *q, *k, *v, *att, *hbuf;
    cudaGetSymbolAddress((void**)&q,    g_q);
    cudaGetSymbolAddress((void**)&k,    g_k);
    cudaGetSymbolAddress((void**)&v,    g_v);
    cudaGetSymbolAddress((void**)&att,  g_att);
    cudaGetSymbolAddress((void**)&hbuf, g_h);

    const int M = B_ * N_;
    const size_t gemm_smem = 2u * 128u * 128u * sizeof(float);  // 128 KB
    const size_t attn_smem = 3u * 128u * HS * 2u;               // 104448 B
    cudaFuncSetAttribute(gemm128, cudaFuncAttributeMaxDynamicSharedMemorySize, (int)gemm_smem);
    cudaFuncSetAttribute(attn_f16, cudaFuncAttributeMaxDynamicSharedMemorySize, (int)attn_smem);

    gemm128<<<M / 128, 256, gemm_smem>>>(x, Wq, bq, nullptr, q, 0);
    gemm128<<<M / 128, 256, gemm_smem>>>(x, Wk, bk, nullptr, k, 0);
    gemm128<<<M / 128, 256, gemm_smem>>>(x, Wv, bv, nullptr, v, 0);

    dim3 ag(N_ / 128, B_);
    attn_f16<<<ag, 512, attn_smem>>>(q, k, v, adj, x, att);

    gemm128<<<M / 128, 256, gemm_smem>>>(att, W1, b1, nullptr, hbuf, 1);
    gemm128<<<M / 128, 256, gemm_smem>>>(hbuf, W2, b2, att, out, 1);
}

// round 7
// speedup vs baseline: 5.8473x; 1.1863x over previous
#include <cuda_runtime.h>
#include <cuda_fp16.h>
#include <cstdint>
#include <math.h>

#define B_ 4
#define N_ 4096
#define D_ 128
#define HS 136   // halves per smem row (272B stride: conflict-free ldmatrix)
#define TILE_H (128u * HS * 2u)   // 34816 B per 128-row fp16 tile

// ---------------- scratch (device globals; no runtime allocation) ----------
__device__ float g_q[B_ * N_ * D_];
__device__ float g_k[B_ * N_ * D_];
__device__ float g_v[B_ * N_ * D_];
__device__ float g_att[B_ * N_ * D_];
__device__ float g_h[B_ * N_ * D_];

// ======================= helpers ===========================================
__device__ __forceinline__ uint32_t smem_u32(const void* p) {
    uint32_t a;
    asm("{ .reg .u64 t; cvta.to.shared.u64 t, %1; cvt.u32.u64 %0, t; }"
        : "=r"(a) : "l"(p));
    return a;
}

__device__ __forceinline__ float ex2f(float x) {
    float r;
    asm("ex2.approx.ftz.f32 %0, %1;" : "=f"(r) : "f"(x));
    return r;
}

__device__ __forceinline__ uint32_t f2h2(float a, float b) {
    __half2 h = __floats2half2_rn(a, b);
    return *reinterpret_cast<uint32_t*>(&h);
}

__device__ __forceinline__ void sts64(uint32_t addr, uint32_t lo, uint32_t hi) {
    asm volatile("st.shared.v2.b32 [%0], {%1,%2};" :: "r"(addr), "r"(lo), "r"(hi) : "memory");
}
__device__ __forceinline__ void sts32u(uint32_t addr, uint32_t v) {
    asm volatile("st.shared.b32 [%0], %1;" :: "r"(addr), "r"(v) : "memory");
}

__device__ __forceinline__ void ldsm_x4(uint32_t& r0, uint32_t& r1, uint32_t& r2, uint32_t& r3,
                                        uint32_t addr) {
    asm volatile("ldmatrix.sync.aligned.m8n8.x4.shared.b16 {%0,%1,%2,%3}, [%4];"
        : "=r"(r0), "=r"(r1), "=r"(r2), "=r"(r3) : "r"(addr));
}
__device__ __forceinline__ void ldsm_x4_t(uint32_t& r0, uint32_t& r1, uint32_t& r2, uint32_t& r3,
                                          uint32_t addr) {
    asm volatile("ldmatrix.sync.aligned.m8n8.x4.trans.shared.b16 {%0,%1,%2,%3}, [%4];"
        : "=r"(r0), "=r"(r1), "=r"(r2), "=r"(r3) : "r"(addr));
}

// D(16x8,f32) += A(16x16,f16 row) * B(16x8,f16 col)
__device__ __forceinline__ void mma_f16(float* d,
                                        uint32_t a0, uint32_t a1, uint32_t a2, uint32_t a3,
                                        uint32_t b0, uint32_t b1) {
    asm volatile(
        "mma.sync.aligned.m16n8k16.row.col.f32.f16.f16.f32 "
        "{%0,%1,%2,%3}, {%4,%5,%6,%7}, {%8,%9}, {%0,%1,%2,%3};"
        : "+f"(d[0]), "+f"(d[1]), "+f"(d[2]), "+f"(d[3])
        : "r"(a0), "r"(a1), "r"(a2), "r"(a3), "r"(b0), "r"(b1));
}

// ---------------------------------------------------------------------------
// fp16 flash attention, fixed-shift softmax (C=3), Q register-resident:
//   S = Q K^T ; P = exp(S*scale + adj + eye - C) ; l += rowsum(P) ; O += P V
//   out = relu(O/l) + x
// 256 thr = 8 warps, 4x2 grid: w_m = wid&3 (32 q-rows), w_n = wid>>2 (64 cols)
// Smem: Kb[128][HS], Vb[128][HS], Pb[128][HS] (Q staged in Pb in prologue)
// ---------------------------------------------------------------------------
__global__ __launch_bounds__(256, 1) void attn_f16(
    const float* __restrict__ Q, const float* __restrict__ K,
    const float* __restrict__ V, const float* __restrict__ adj,
    const float* __restrict__ X, float* __restrict__ Out)
{
    extern __shared__ __align__(16) char smraw[];
    const uint32_t Kb = smem_u32(smraw);
    const uint32_t Vb = Kb + TILE_H;
    const uint32_t Pb = Kb + 2u * TILE_H;     // Q staging in prologue, then P
    __shared__ float l_part[2][128];

    const int tid  = threadIdx.x;
    const int wid  = tid >> 5;
    const int lane = tid & 31;
    const int w_m  = wid & 3;      // q-row group: 32 rows
    const int w_n  = wid >> 2;     // col group:   64 cols
    const int gq   = lane >> 2;
    const int tq   = lane & 3;
    const int lr   = lane & 7;
    const int g8   = lane >> 3;
    const int b    = blockIdx.y;
    const int q0   = blockIdx.x * 128;

    // ldmatrix per-lane address components (validated in R6)
    const int arow = lr + ((g8 & 1) ? 8 : 0);   // A-type (Q/P): rows m, cols k
    const int acol = (g8 & 2) ? 8 : 0;
    const int brow = lr + ((g8 & 2) ? 8 : 0);   // B-type (K/W): rows n, cols k
    const int bcol = (g8 & 1) ? 8 : 0;
    const int vrow = lr + ((g8 & 1) ? 8 : 0);   // B-trans (V):  rows kv, cols d
    const int vcol = (g8 & 2) ? 8 : 0;

    // ---- prologue: stage Q (fp16) into Pb, then lift fragments to registers
    {
        const float4* Qg = reinterpret_cast<const float4*>(Q + ((size_t)b * N_ + q0) * D_);
#pragma unroll
        for (int it = 0; it < 16; ++it) {
            int idx = tid + it * 256;          // 4096 float4 = 128 x 32
            int r = idx >> 5, c4 = idx & 31;
            float4 v4 = Qg[idx];
            sts64(Pb + (uint32_t)(r * HS + c4 * 4) * 2u,
                  f2h2(v4.x, v4.y), f2h2(v4.z, v4.w));
        }
    }
    __syncthreads();

    uint32_t qa[8][2][4];
#pragma unroll
    for (int ks = 0; ks < 8; ++ks)
#pragma unroll
        for (int mi = 0; mi < 2; ++mi)
            ldsm_x4(qa[ks][mi][0], qa[ks][mi][1], qa[ks][mi][2], qa[ks][mi][3],
                    Pb + (uint32_t)((w_m * 32 + mi * 16 + arow) * HS + ks * 16 + acol) * 2u);

    const float scaleL = 0.088388347648318447f * 1.4426950408889634f;  // scale*log2e
    const float LOG2E  = 1.4426950408889634f;
    const float C      = 3.0f;

    float lsum[4];
    float Oacc[2][8][4];
#pragma unroll
    for (int i = 0; i < 4; ++i) lsum[i] = 0.f;
#pragma unroll
    for (int mi = 0; mi < 2; ++mi)
#pragma unroll
        for (int nt = 0; nt < 8; ++nt)
#pragma unroll
            for (int j = 0; j < 4; ++j) Oacc[mi][nt][j] = 0.f;

    for (int ct = 0; ct < N_ / 128; ++ct) {
        __syncthreads();   // prev iter MMA2 done reading Vb/Pb (and prologue ldsm done)
        // ---- stage K, V (fp16) ----
        {
            const float4* Kg = reinterpret_cast<const float4*>(K + ((size_t)b * N_ + ct * 128) * D_);
            const float4* Vg = reinterpret_cast<const float4*>(V + ((size_t)b * N_ + ct * 128) * D_);
#pragma unroll
            for (int it = 0; it < 16; ++it) {
                int idx = tid + it * 256;
                int r = idx >> 5, c4 = idx & 31;
                uint32_t off = (uint32_t)(r * HS + c4 * 4) * 2u;
                float4 k4 = Kg[idx];
                sts64(Kb + off, f2h2(k4.x, k4.y), f2h2(k4.z, k4.w));
                float4 v4 = Vg[idx];
                sts64(Vb + off, f2h2(v4.x, v4.y), f2h2(v4.z, v4.w));
            }
        }
        __syncthreads();

        // ---- MMA1: S = Q(regs) @ K^T  (warp tile 32x64) ----
        float Sacc[2][8][4];
#pragma unroll
        for (int mi = 0; mi < 2; ++mi)
#pragma unroll
            for (int nt = 0; nt < 8; ++nt)
#pragma unroll
                for (int j = 0; j < 4; ++j) Sacc[mi][nt][j] = 0.f;

#pragma unroll
        for (int ks = 0; ks < 8; ++ks) {
#pragma unroll
            for (int np = 0; np < 4; ++np) {
                uint32_t r0, r1, r2, r3;
                ldsm_x4(r0, r1, r2, r3,
                        Kb + (uint32_t)((w_n * 64 + np * 16 + brow) * HS + ks * 16 + bcol) * 2u);
#pragma unroll
                for (int mi = 0; mi < 2; ++mi) {
                    mma_f16(Sacc[mi][np * 2],     qa[ks][mi][0], qa[ks][mi][1], qa[ks][mi][2], qa[ks][mi][3], r0, r1);
                    mma_f16(Sacc[mi][np * 2 + 1], qa[ks][mi][0], qa[ks][mi][1], qa[ks][mi][2], qa[ks][mi][3], r2, r3);
                }
            }
        }

        // ---- softmax (fixed shift) + direct P store into Pb ----
        // (Pb is not read by MMA1; prev MMA2 reads were fenced by loop-top sync)
#pragma unroll
        for (int mi = 0; mi < 2; ++mi) {
            const int tr0 = q0 + w_m * 32 + mi * 16 + gq;
            const int tr1 = tr0 + 8;
            const int rl0 = w_m * 32 + mi * 16 + gq;
#pragma unroll
            for (int nt = 0; nt < 8; ++nt) {
                int cg = ct * 128 + w_n * 64 + nt * 8 + 2 * tq;
                float2 aj0 = *reinterpret_cast<const float2*>(adj + (size_t)tr0 * N_ + cg);
                float2 aj1 = *reinterpret_cast<const float2*>(adj + (size_t)tr1 * N_ + cg);
                float p0 = ex2f(fmaf(Sacc[mi][nt][0], scaleL,
                                     (aj0.x + ((tr0 == cg)     ? 1.f : 0.f) - C) * LOG2E));
                float p1 = ex2f(fmaf(Sacc[mi][nt][1], scaleL,
                                     (aj0.y + ((tr0 == cg + 1) ? 1.f : 0.f) - C) * LOG2E));
                float p2 = ex2f(fmaf(Sacc[mi][nt][2], scaleL,
                                     (aj1.x + ((tr1 == cg)     ? 1.f : 0.f) - C) * LOG2E));
                float p3 = ex2f(fmaf(Sacc[mi][nt][3], scaleL,
                                     (aj1.y + ((tr1 == cg + 1) ? 1.f : 0.f) - C) * LOG2E));
                lsum[mi * 2 + 0] += p0 + p1;
                lsum[mi * 2 + 1] += p2 + p3;
                int cl = w_n * 64 + nt * 8 + 2 * tq;
                sts32u(Pb + (uint32_t)(rl0 * HS + cl) * 2u,       f2h2(p0, p1));
                sts32u(Pb + (uint32_t)((rl0 + 8) * HS + cl) * 2u, f2h2(p2, p3));
            }
        }
        __syncthreads();   // all P written before cross-warp MMA2 reads

        // ---- MMA2: O += P @ V  (warp tile 32 q x 64 d, k = 128 kv) ----
#pragma unroll
        for (int ks = 0; ks < 8; ++ks) {
            uint32_t pa[2][4];
#pragma unroll
            for (int mi = 0; mi < 2; ++mi)
                ldsm_x4(pa[mi][0], pa[mi][1], pa[mi][2], pa[mi][3],
                        Pb + (uint32_t)((w_m * 32 + mi * 16 + arow) * HS + ks * 16 + acol) * 2u);
#pragma unroll
            for (int np = 0; np < 4; ++np) {
                uint32_t r0, r1, r2, r3;
                ldsm_x4_t(r0, r1, r2, r3,
                          Vb + (uint32_t)((ks * 16 + vrow) * HS + w_n * 64 + np * 16 + vcol) * 2u);
#pragma unroll
                for (int mi = 0; mi < 2; ++mi) {
                    mma_f16(Oacc[mi][np * 2],     pa[mi][0], pa[mi][1], pa[mi][2], pa[mi][3], r0, r1);
                    mma_f16(Oacc[mi][np * 2 + 1], pa[mi][0], pa[mi][1], pa[mi][2], pa[mi][3], r2, r3);
                }
            }
        }
    }

    // ---- epilogue: reduce l across tq lanes and the 2 w_n warps ----
#pragma unroll
    for (int li = 0; li < 4; ++li) {
        lsum[li] += __shfl_xor_sync(0xffffffffu, lsum[li], 1);
        lsum[li] += __shfl_xor_sync(0xffffffffu, lsum[li], 2);
    }
    if (tq == 0) {
#pragma unroll
        for (int mi = 0; mi < 2; ++mi)
#pragma unroll
            for (int hi = 0; hi < 2; ++hi)
                l_part[w_n][w_m * 32 + mi * 16 + hi * 8 + gq] = lsum[mi * 2 + hi];
    }
    __syncthreads();

#pragma unroll
    for (int mi = 0; mi < 2; ++mi)
#pragma unroll
        for (int hi = 0; hi < 2; ++hi) {
            const int rl = w_m * 32 + mi * 16 + hi * 8 + gq;
            const float linv = 1.f / (l_part[0][rl] + l_part[1][rl]);
#pragma unroll
            for (int nt = 0; nt < 8; ++nt) {
                int cl = w_n * 64 + nt * 8 + 2 * tq;
                size_t base = ((size_t)b * N_ + q0 + rl) * D_ + cl;
                float2 x2 = *reinterpret_cast<const float2*>(X + base);
                float2 o;
                o.x = fmaxf(Oacc[mi][nt][hi * 2]     * linv, 0.f) + x2.x;
                o.y = fmaxf(Oacc[mi][nt][hi * 2 + 1] * linv, 0.f) + x2.y;
                *reinterpret_cast<float2*>(Out + base) = o;
            }
        }
}

// ---------------------------------------------------------------------------
// fp16 tensor GEMM: Y[M,128] = act(X[M,128] @ W^T[128,128] + b) (+ resid)
// 256 thr = 8 warps, 4x2 grid, CTA tile 128x128, K=128.
// W rows are the MMA B-operand n-index (Y[i][j] = sum_k X[i][k] * W[j][k]).
// ---------------------------------------------------------------------------
__global__ __launch_bounds__(256) void gemm_f16(
    const float* __restrict__ X, const float* __restrict__ W,
    const float* __restrict__ bias, const float* __restrict__ resid,
    float* __restrict__ Y, int do_relu)
{
    extern __shared__ __align__(16) char smraw[];
    const uint32_t Xb = smem_u32(smraw);
    const uint32_t Wb = Xb + TILE_H;

    const int tid  = threadIdx.x;
    const int wid  = tid >> 5;
    const int lane = tid & 31;
    const int w_m  = wid & 3;
    const int w_n  = wid >> 2;
    const int gq   = lane >> 2;
    const int tq   = lane & 3;
    const int lr   = lane & 7;
    const int g8   = lane >> 3;
    const int row0 = blockIdx.x * 128;

    const int arow = lr + ((g8 & 1) ? 8 : 0);
    const int acol = (g8 & 2) ? 8 : 0;
    const int brow = lr + ((g8 & 2) ? 8 : 0);
    const int bcol = (g8 & 1) ? 8 : 0;

    // ---- stage X and W (fp16) ----
    {
        const float4* Xg = reinterpret_cast<const float4*>(X + (size_t)row0 * D_);
        const float4* Wg = reinterpret_cast<const float4*>(W);
#pragma unroll
        for (int it = 0; it < 16; ++it) {
            int idx = tid + it * 256;
            int r = idx >> 5, c4 = idx & 31;
            uint32_t off = (uint32_t)(r * HS + c4 * 4) * 2u;
            float4 x4 = Xg[idx];
            sts64(Xb + off, f2h2(x4.x, x4.y), f2h2(x4.z, x4.w));
            float4 w4 = Wg[idx];
            sts64(Wb + off, f2h2(w4.x, w4.y), f2h2(w4.z, w4.w));
        }
    }
    __syncthreads();

    float acc[2][8][4];
#pragma unroll
    for (int mi = 0; mi < 2; ++mi)
#pragma unroll
        for (int nt = 0; nt < 8; ++nt)
#pragma unroll
            for (int j = 0; j < 4; ++j) acc[mi][nt][j] = 0.f;

#pragma unroll
    for (int ks = 0; ks < 8; ++ks) {
        uint32_t xa[2][4];
#pragma unroll
        for (int mi = 0; mi < 2; ++mi)
            ldsm_x4(xa[mi][0], xa[mi][1], xa[mi][2], xa[mi][3],
                    Xb + (uint32_t)((w_m * 32 + mi * 16 + arow) * HS + ks * 16 + acol) * 2u);
#pragma unroll
        for (int np = 0; np < 4; ++np) {
            uint32_t r0, r1, r2, r3;
            ldsm_x4(r0, r1, r2, r3,
                    Wb + (uint32_t)((w_n * 64 + np * 16 + brow) * HS + ks * 16 + bcol) * 2u);
#pragma unroll
            for (int mi = 0; mi < 2; ++mi) {
                mma_f16(acc[mi][np * 2],     xa[mi][0], xa[mi][1], xa[mi][2], xa[mi][3], r0, r1);
                mma_f16(acc[mi][np * 2 + 1], xa[mi][0], xa[mi][1], xa[mi][2], xa[mi][3], r2, r3);
            }
        }
    }

    // ---- epilogue ----
#pragma unroll
    for (int mi = 0; mi < 2; ++mi)
#pragma unroll
        for (int hi = 0; hi < 2; ++hi) {
            const int row = row0 + w_m * 32 + mi * 16 + hi * 8 + gq;
#pragma unroll
            for (int nt = 0; nt < 8; ++nt) {
                int col = w_n * 64 + nt * 8 + 2 * tq;
                float2 bb = *reinterpret_cast<const float2*>(bias + col);
                float v0 = acc[mi][nt][hi * 2]     + bb.x;
                float v1 = acc[mi][nt][hi * 2 + 1] + bb.y;
                if (do_relu) { v0 = fmaxf(v0, 0.f); v1 = fmaxf(v1, 0.f); }
                size_t base = (size_t)row * D_ + col;
                if (resid) {
                    float2 r2 = *reinterpret_cast<const float2*>(resid + base);
                    v0 += r2.x; v1 += r2.y;
                }
                *reinterpret_cast<float2*>(Y + base) = make_float2(v0, v1);
            }
        }
}

// ---------------------------------------------------------------------------
extern "C" void kernel_launch(void* const* d_in, const int* in_sizes, int n_in,
                              void* d_out, int out_size)
{
    const float* x   = (const float*)d_in[0];
    const float* adj = (const float*)d_in[1];
    const float* Wq  = (const float*)d_in[2];
    const float* bq  = (const float*)d_in[3];
    const float* Wk  = (const float*)d_in[4];
    const float* bk  = (const float*)d_in[5];
    const float* Wv  = (const float*)d_in[6];
    const float* bv  = (const float*)d_in[7];
    const float* W1  = (const float*)d_in[8];
    const float* b1  = (const float*)d_in[9];
    const float* W2  = (const float*)d_in[10];
    const float* b2  = (const float*)d_in[11];
    float* out = (float*)d_out;

    float *q, *k, *v, *att, *hbuf;
    cudaGetSymbolAddress((void**)&q,    g_q);
    cudaGetSymbolAddress((void**)&k,    g_k);
    cudaGetSymbolAddress((void**)&v,    g_v);
    cudaGetSymbolAddress((void**)&att,  g_att);
    cudaGetSymbolAddress((void**)&hbuf, g_h);

    const int M = B_ * N_;
    const size_t gemm_smem = 2u * TILE_H;   // 69632 B
    const size_t attn_smem = 3u * TILE_H;   // 104448 B
    cudaFuncSetAttribute(gemm_f16, cudaFuncAttributeMaxDynamicSharedMemorySize, (int)gemm_smem);
    cudaFuncSetAttribute(attn_f16, cudaFuncAttributeMaxDynamicSharedMemorySize, (int)attn_smem);

    gemm_f16<<<M / 128, 256, gemm_smem>>>(x, Wq, bq, nullptr, q, 0);
    gemm_f16<<<M / 128, 256, gemm_smem>>>(x, Wk, bk, nullptr, k, 0);
    gemm_f16<<<M / 128, 256, gemm_smem>>>(x, Wv, bv, nullptr, v, 0);

    dim3 ag(N_ / 128, B_);
    attn_f16<<<ag, 256, attn_smem>>>(q, k, v, adj, x, att);

    gemm_f16<<<M / 128, 256, gemm_smem>>>(att, W1, b1, nullptr, hbuf, 1);
    gemm_f16<<<M / 128, 256, gemm_smem>>>(hbuf, W2, b2, att, out, 1);
}

// round 8
// speedup vs baseline: 6.2726x; 1.0727x over previous
#include <cuda_runtime.h>
#include <cuda_fp16.h>
#include <cstdint>
#include <math.h>

#define B_ 4
#define N_ 4096
#define D_ 128
#define HS 136                    // halves per smem row (272B stride)
#define TILE_H (128u * HS * 2u)   // 34816 B per 128-row fp16 tile
#define NT (N_ / 128)

// ---------------- scratch (device globals; no runtime allocation) ----------
__device__ __half g_q[B_ * N_ * D_];
__device__ __half g_k[B_ * N_ * D_];
__device__ __half g_v[B_ * N_ * D_];
__device__ float  g_att[B_ * N_ * D_];
__device__ float  g_h[B_ * N_ * D_];

// ======================= helpers ===========================================
__device__ __forceinline__ uint32_t smem_u32(const void* p) {
    uint32_t a;
    asm("{ .reg .u64 t; cvta.to.shared.u64 t, %1; cvt.u32.u64 %0, t; }"
        : "=r"(a) : "l"(p));
    return a;
}

__device__ __forceinline__ float ex2f(float x) {
    float r;
    asm("ex2.approx.ftz.f32 %0, %1;" : "=f"(r) : "f"(x));
    return r;
}

__device__ __forceinline__ uint32_t f2h2(float a, float b) {
    __half2 h = __floats2half2_rn(a, b);
    return *reinterpret_cast<uint32_t*>(&h);
}

__device__ __forceinline__ void sts64(uint32_t addr, uint32_t lo, uint32_t hi) {
    asm volatile("st.shared.v2.b32 [%0], {%1,%2};" :: "r"(addr), "r"(lo), "r"(hi) : "memory");
}
__device__ __forceinline__ void sts32u(uint32_t addr, uint32_t v) {
    asm volatile("st.shared.b32 [%0], %1;" :: "r"(addr), "r"(v) : "memory");
}

__device__ __forceinline__ void cp16(uint32_t dst, const void* src) {
    asm volatile("cp.async.cg.shared.global [%0], [%1], 16;"
        :: "r"(dst), "l"(src) : "memory");
}
#define CP_COMMIT() asm volatile("cp.async.commit_group;" ::: "memory")
#define CP_WAIT0()  asm volatile("cp.async.wait_group 0;" ::: "memory")

__device__ __forceinline__ void ldsm_x4(uint32_t& r0, uint32_t& r1, uint32_t& r2, uint32_t& r3,
                                        uint32_t addr) {
    asm volatile("ldmatrix.sync.aligned.m8n8.x4.shared.b16 {%0,%1,%2,%3}, [%4];"
        : "=r"(r0), "=r"(r1), "=r"(r2), "=r"(r3) : "r"(addr));
}
__device__ __forceinline__ void ldsm_x4_t(uint32_t& r0, uint32_t& r1, uint32_t& r2, uint32_t& r3,
                                          uint32_t addr) {
    asm volatile("ldmatrix.sync.aligned.m8n8.x4.trans.shared.b16 {%0,%1,%2,%3}, [%4];"
        : "=r"(r0), "=r"(r1), "=r"(r2), "=r"(r3) : "r"(addr));
}

// D(16x8,f32) += A(16x16,f16 row) * B(16x8,f16 col)
__device__ __forceinline__ void mma_f16(float* d,
                                        uint32_t a0, uint32_t a1, uint32_t a2, uint32_t a3,
                                        uint32_t b0, uint32_t b1) {
    asm volatile(
        "mma.sync.aligned.m16n8k16.row.col.f32.f16.f16.f32 "
        "{%0,%1,%2,%3}, {%4,%5,%6,%7}, {%8,%9}, {%0,%1,%2,%3};"
        : "+f"(d[0]), "+f"(d[1]), "+f"(d[2]), "+f"(d[3])
        : "r"(a0), "r"(a1), "r"(a2), "r"(a3), "r"(b0), "r"(b1));
}

// ---------------------------------------------------------------------------
// fp16 flash attention, fixed-shift softmax (C=3), cp.async double-buffered:
//   S = Q K^T ; P = exp(S*scale + adj + eye - C) ; l += rowsum(P) ; O += P V
//   out = relu(O/l) + x
// 512 thr = 16 warps, 4x4 grid: w_m = wid&3 (32 q-rows), w_n = wid>>2 (32 cols)
// Smem (fp16 tiles): Qh | K0 | V0 | K1 | V1 | P      = 6 * 34816 B
// ---------------------------------------------------------------------------
__global__ __launch_bounds__(512, 1) void attn_f16(
    const __half* __restrict__ Q, const __half* __restrict__ K,
    const __half* __restrict__ V, const float* __restrict__ adj,
    const float* __restrict__ X, float* __restrict__ Out)
{
    extern __shared__ __align__(16) char smraw[];
    const uint32_t Qb = smem_u32(smraw);
    __shared__ float l_part[4][128];

    const int tid  = threadIdx.x;
    const int wid  = tid >> 5;
    const int lane = tid & 31;
    const int w_m  = wid & 3;      // q-row group: 32 rows
    const int w_n  = wid >> 2;     // col group:   32 cols
    const int gq   = lane >> 2;
    const int tq   = lane & 3;
    const int lr   = lane & 7;
    const int g8   = lane >> 3;
    const int b    = blockIdx.y;
    const int q0   = blockIdx.x * 128;

    // ldmatrix per-lane address components (validated R6)
    const int arow = lr + ((g8 & 1) ? 8 : 0);   // A-type (Q/P)
    const int acol = (g8 & 2) ? 8 : 0;
    const int brow = lr + ((g8 & 2) ? 8 : 0);   // B-type (K)
    const int bcol = (g8 & 1) ? 8 : 0;
    const int vrow = lr + ((g8 & 1) ? 8 : 0);   // B-trans (V)
    const int vcol = (g8 & 2) ? 8 : 0;

    // tile bases: Q, K0, V0, K1, V1, P
    const uint32_t Kt[2] = { Qb + 1u * TILE_H, Qb + 3u * TILE_H };
    const uint32_t Vt[2] = { Qb + 2u * TILE_H, Qb + 4u * TILE_H };
    const uint32_t Pb    = Qb + 5u * TILE_H;

    // ---- prologue: cp.async Q + K0 + V0 ----
    {
        const __half* Qg = Q + ((size_t)b * N_ + q0) * D_;
        const __half* Kg = K + ((size_t)b * N_) * D_;
        const __half* Vg = V + ((size_t)b * N_) * D_;
#pragma unroll
        for (int it = 0; it < 4; ++it) {
            int idx = tid + it * 512;          // 2048 16B-chunks per tile
            int r = idx >> 4, c = idx & 15;
            uint32_t off = (uint32_t)(r * HS + c * 8) * 2u;
            const size_t gsrc = (size_t)r * D_ + c * 8;
            cp16(Qb    + off, Qg + gsrc);
            cp16(Kt[0] + off, Kg + gsrc);
            cp16(Vt[0] + off, Vg + gsrc);
        }
    }
    CP_COMMIT();
    CP_WAIT0();
    __syncthreads();

    const float scaleL = 0.088388347648318447f * 1.4426950408889634f;  // scale*log2e
    const float LOG2E  = 1.4426950408889634f;
    const float C      = 3.0f;

    float lsum[4];
    float Oacc[2][4][4];
#pragma unroll
    for (int i = 0; i < 4; ++i) lsum[i] = 0.f;
#pragma unroll
    for (int mi = 0; mi < 2; ++mi)
#pragma unroll
        for (int nt = 0; nt < 4; ++nt)
#pragma unroll
            for (int j = 0; j < 4; ++j) Oacc[mi][nt][j] = 0.f;

    for (int ct = 0; ct < NT; ++ct) {
        const uint32_t Kb = Kt[ct & 1];
        const uint32_t Vb = Vt[ct & 1];

        // ---- prefetch next K/V into the other buffer (overlaps compute) ----
        if (ct + 1 < NT) {
            const __half* Kg = K + ((size_t)b * N_ + (ct + 1) * 128) * D_;
            const __half* Vg = V + ((size_t)b * N_ + (ct + 1) * 128) * D_;
            const uint32_t kd = Kt[(ct + 1) & 1];
            const uint32_t vd = Vt[(ct + 1) & 1];
#pragma unroll
            for (int it = 0; it < 4; ++it) {
                int idx = tid + it * 512;
                int r = idx >> 4, c = idx & 15;
                uint32_t off = (uint32_t)(r * HS + c * 8) * 2u;
                const size_t gsrc = (size_t)r * D_ + c * 8;
                cp16(kd + off, Kg + gsrc);
                cp16(vd + off, Vg + gsrc);
            }
            CP_COMMIT();
        }

        // ---- MMA1: S = Q @ K^T  (warp tile 32x32) ----
        float Sacc[2][4][4];
#pragma unroll
        for (int mi = 0; mi < 2; ++mi)
#pragma unroll
            for (int nt = 0; nt < 4; ++nt)
#pragma unroll
                for (int j = 0; j < 4; ++j) Sacc[mi][nt][j] = 0.f;

#pragma unroll
        for (int ks = 0; ks < 8; ++ks) {
            uint32_t qa[2][4];
#pragma unroll
            for (int mi = 0; mi < 2; ++mi)
                ldsm_x4(qa[mi][0], qa[mi][1], qa[mi][2], qa[mi][3],
                        Qb + (uint32_t)((w_m * 32 + mi * 16 + arow) * HS + ks * 16 + acol) * 2u);
#pragma unroll
            for (int np = 0; np < 2; ++np) {
                uint32_t r0, r1, r2, r3;
                ldsm_x4(r0, r1, r2, r3,
                        Kb + (uint32_t)((w_n * 32 + np * 16 + brow) * HS + ks * 16 + bcol) * 2u);
#pragma unroll
                for (int mi = 0; mi < 2; ++mi) {
                    mma_f16(Sacc[mi][np * 2],     qa[mi][0], qa[mi][1], qa[mi][2], qa[mi][3], r0, r1);
                    mma_f16(Sacc[mi][np * 2 + 1], qa[mi][0], qa[mi][1], qa[mi][2], qa[mi][3], r2, r3);
                }
            }
        }

        // ---- softmax (fixed shift) + direct P store into Pb ----
#pragma unroll
        for (int mi = 0; mi < 2; ++mi) {
            const int tr0 = q0 + w_m * 32 + mi * 16 + gq;
            const int tr1 = tr0 + 8;
            const int rl0 = w_m * 32 + mi * 16 + gq;
#pragma unroll
            for (int nt = 0; nt < 4; ++nt) {
                int cg = ct * 128 + w_n * 32 + nt * 8 + 2 * tq;
                float2 aj0 = *reinterpret_cast<const float2*>(adj + (size_t)tr0 * N_ + cg);
                float2 aj1 = *reinterpret_cast<const float2*>(adj + (size_t)tr1 * N_ + cg);
                float p0 = ex2f(fmaf(Sacc[mi][nt][0], scaleL,
                                     (aj0.x + ((tr0 == cg)     ? 1.f : 0.f) - C) * LOG2E));
                float p1 = ex2f(fmaf(Sacc[mi][nt][1], scaleL,
                                     (aj0.y + ((tr0 == cg + 1) ? 1.f : 0.f) - C) * LOG2E));
                float p2 = ex2f(fmaf(Sacc[mi][nt][2], scaleL,
                                     (aj1.x + ((tr1 == cg)     ? 1.f : 0.f) - C) * LOG2E));
                float p3 = ex2f(fmaf(Sacc[mi][nt][3], scaleL,
                                     (aj1.y + ((tr1 == cg + 1) ? 1.f : 0.f) - C) * LOG2E));
                lsum[mi * 2 + 0] += p0 + p1;
                lsum[mi * 2 + 1] += p2 + p3;
                int cl = w_n * 32 + nt * 8 + 2 * tq;
                sts32u(Pb + (uint32_t)(rl0 * HS + cl) * 2u,       f2h2(p0, p1));
                sts32u(Pb + (uint32_t)((rl0 + 8) * HS + cl) * 2u, f2h2(p2, p3));
            }
        }
        __syncthreads();   // P complete before cross-warp MMA2 reads

        // ---- MMA2: O += P @ V  (warp tile 32 q x 32 d, k = 128 kv) ----
#pragma unroll
        for (int ks = 0; ks < 8; ++ks) {
            uint32_t pa[2][4];
#pragma unroll
            for (int mi = 0; mi < 2; ++mi)
                ldsm_x4(pa[mi][0], pa[mi][1], pa[mi][2], pa[mi][3],
                        Pb + (uint32_t)((w_m * 32 + mi * 16 + arow) * HS + ks * 16 + acol) * 2u);
#pragma unroll
            for (int np = 0; np < 2; ++np) {
                uint32_t r0, r1, r2, r3;
                ldsm_x4_t(r0, r1, r2, r3,
                          Vb + (uint32_t)((ks * 16 + vrow) * HS + w_n * 32 + np * 16 + vcol) * 2u);
#pragma unroll
                for (int mi = 0; mi < 2; ++mi) {
                    mma_f16(Oacc[mi][np * 2],     pa[mi][0], pa[mi][1], pa[mi][2], pa[mi][3], r0, r1);
                    mma_f16(Oacc[mi][np * 2 + 1], pa[mi][0], pa[mi][1], pa[mi][2], pa[mi][3], r2, r3);
                }
            }
        }

        CP_WAIT0();        // next K/V landed (had all of compute to arrive)
        __syncthreads();   // visibility + all warps done with this iter's buffers
    }

    // ---- epilogue: reduce l across tq lanes and the 4 w_n warps ----
#pragma unroll
    for (int li = 0; li < 4; ++li) {
        lsum[li] += __shfl_xor_sync(0xffffffffu, lsum[li], 1);
        lsum[li] += __shfl_xor_sync(0xffffffffu, lsum[li], 2);
    }
    if (tq == 0) {
#pragma unroll
        for (int mi = 0; mi < 2; ++mi)
#pragma unroll
            for (int hi = 0; hi < 2; ++hi)
                l_part[w_n][w_m * 32 + mi * 16 + hi * 8 + gq] = lsum[mi * 2 + hi];
    }
    __syncthreads();

#pragma unroll
    for (int mi = 0; mi < 2; ++mi)
#pragma unroll
        for (int hi = 0; hi < 2; ++hi) {
            const int rl = w_m * 32 + mi * 16 + hi * 8 + gq;
            const float linv = 1.f / (l_part[0][rl] + l_part[1][rl] +
                                      l_part[2][rl] + l_part[3][rl]);
#pragma unroll
            for (int nt = 0; nt < 4; ++nt) {
                int cl = w_n * 32 + nt * 8 + 2 * tq;
                size_t base = ((size_t)b * N_ + q0 + rl) * D_ + cl;
                float2 x2 = *reinterpret_cast<const float2*>(X + base);
                float2 o;
                o.x = fmaxf(Oacc[mi][nt][hi * 2]     * linv, 0.f) + x2.x;
                o.y = fmaxf(Oacc[mi][nt][hi * 2 + 1] * linv, 0.f) + x2.y;
                *reinterpret_cast<float2*>(Out + base) = o;
            }
        }
}

// ---------------------------------------------------------------------------
// fp16 tensor GEMM: Y[M,128] = act(X[M,128] @ W^T[128,128] + b) (+ resid)
// out_half: write __half output (for QKV), else float.
// 256 thr = 8 warps, 4x2 grid, CTA tile 128x128, K=128. (validated R7)
// ---------------------------------------------------------------------------
__global__ __launch_bounds__(256) void gemm_f16(
    const float* __restrict__ X, const float* __restrict__ W,
    const float* __restrict__ bias, const float* __restrict__ resid,
    void* __restrict__ Yv, int do_relu, int out_half)
{
    extern __shared__ __align__(16) char smraw[];
    const uint32_t Xb = smem_u32(smraw);
    const uint32_t Wb = Xb + TILE_H;

    const int tid  = threadIdx.x;
    const int wid  = tid >> 5;
    const int lane = tid & 31;
    const int w_m  = wid & 3;
    const int w_n  = wid >> 2;
    const int gq   = lane >> 2;
    const int tq   = lane & 3;
    const int lr   = lane & 7;
    const int g8   = lane >> 3;
    const int row0 = blockIdx.x * 128;

    const int arow = lr + ((g8 & 1) ? 8 : 0);
    const int acol = (g8 & 2) ? 8 : 0;
    const int brow = lr + ((g8 & 2) ? 8 : 0);
    const int bcol = (g8 & 1) ? 8 : 0;

    {
        const float4* Xg = reinterpret_cast<const float4*>(X + (size_t)row0 * D_);
        const float4* Wg = reinterpret_cast<const float4*>(W);
#pragma unroll
        for (int it = 0; it < 16; ++it) {
            int idx = tid + it * 256;
            int r = idx >> 5, c4 = idx & 31;
            uint32_t off = (uint32_t)(r * HS + c4 * 4) * 2u;
            float4 x4 = Xg[idx];
            sts64(Xb + off, f2h2(x4.x, x4.y), f2h2(x4.z, x4.w));
            float4 w4 = Wg[idx];
            sts64(Wb + off, f2h2(w4.x, w4.y), f2h2(w4.z, w4.w));
        }
    }
    __syncthreads();

    float acc[2][8][4];
#pragma unroll
    for (int mi = 0; mi < 2; ++mi)
#pragma unroll
        for (int nt = 0; nt < 8; ++nt)
#pragma unroll
            for (int j = 0; j < 4; ++j) acc[mi][nt][j] = 0.f;

#pragma unroll
    for (int ks = 0; ks < 8; ++ks) {
        uint32_t xa[2][4];
#pragma unroll
        for (int mi = 0; mi < 2; ++mi)
            ldsm_x4(xa[mi][0], xa[mi][1], xa[mi][2], xa[mi][3],
                    Xb + (uint32_t)((w_m * 32 + mi * 16 + arow) * HS + ks * 16 + acol) * 2u);
#pragma unroll
        for (int np = 0; np < 4; ++np) {
            uint32_t r0, r1, r2, r3;
            ldsm_x4(r0, r1, r2, r3,
                    Wb + (uint32_t)((w_n * 64 + np * 16 + brow) * HS + ks * 16 + bcol) * 2u);
#pragma unroll
            for (int mi = 0; mi < 2; ++mi) {
                mma_f16(acc[mi][np * 2],     xa[mi][0], xa[mi][1], xa[mi][2], xa[mi][3], r0, r1);
                mma_f16(acc[mi][np * 2 + 1], xa[mi][0], xa[mi][1], xa[mi][2], xa[mi][3], r2, r3);
            }
        }
    }

#pragma unroll
    for (int mi = 0; mi < 2; ++mi)
#pragma unroll
        for (int hi = 0; hi < 2; ++hi) {
            const int row = row0 + w_m * 32 + mi * 16 + hi * 8 + gq;
#pragma unroll
            for (int nt = 0; nt < 8; ++nt) {
                int col = w_n * 64 + nt * 8 + 2 * tq;
                float2 bb = *reinterpret_cast<const float2*>(bias + col);
                float v0 = acc[mi][nt][hi * 2]     + bb.x;
                float v1 = acc[mi][nt][hi * 2 + 1] + bb.y;
                if (do_relu) { v0 = fmaxf(v0, 0.f); v1 = fmaxf(v1, 0.f); }
                size_t base = (size_t)row * D_ + col;
                if (resid) {
                    float2 r2 = *reinterpret_cast<const float2*>(resid + base);
                    v0 += r2.x; v1 += r2.y;
                }
                if (out_half) {
                    *reinterpret_cast<uint32_t*>(reinterpret_cast<__half*>(Yv) + base) =
                        f2h2(v0, v1);
                } else {
                    *reinterpret_cast<float2*>(reinterpret_cast<float*>(Yv) + base) =
                        make_float2(v0, v1);
                }
            }
        }
}

// ---------------------------------------------------------------------------
extern "C" void kernel_launch(void* const* d_in, const int* in_sizes, int n_in,
                              void* d_out, int out_size)
{
    const float* x   = (const float*)d_in[0];
    const float* adj = (const float*)d_in[1];
    const float* Wq  = (const float*)d_in[2];
    const float* bq  = (const float*)d_in[3];
    const float* Wk  = (const float*)d_in[4];
    const float* bk  = (const float*)d_in[5];
    const float* Wv  = (const float*)d_in[6];
    const float* bv  = (const float*)d_in[7];
    const float* W1  = (const float*)d_in[8];
    const float* b1  = (const float*)d_in[9];
    const float* W2  = (const float*)d_in[10];
    const float* b2  = (const float*)d_in[11];
    float* out = (float*)d_out;

    __half *q, *k, *v;
    float *att, *hbuf;
    cudaGetSymbolAddress((void**)&q,    g_q);
    cudaGetSymbolAddress((void**)&k,    g_k);
    cudaGetSymbolAddress((void**)&v,    g_v);
    cudaGetSymbolAddress((void**)&att,  g_att);
    cudaGetSymbolAddress((void**)&hbuf, g_h);

    const int M = B_ * N_;
    const size_t gemm_smem = 2u * TILE_H;   // 69632 B
    const size_t attn_smem = 6u * TILE_H;   // 208896 B
    cudaFuncSetAttribute(gemm_f16, cudaFuncAttributeMaxDynamicSharedMemorySize, (int)gemm_smem);
    cudaFuncSetAttribute(attn_f16, cudaFuncAttributeMaxDynamicSharedMemorySize, (int)attn_smem);

    gemm_f16<<<M / 128, 256, gemm_smem>>>(x, Wq, bq, nullptr, q, 0, 1);
    gemm_f16<<<M / 128, 256, gemm_smem>>>(x, Wk, bk, nullptr, k, 0, 1);
    gemm_f16<<<M / 128, 256, gemm_smem>>>(x, Wv, bv, nullptr, v, 0, 1);

    dim3 ag(N_ / 128, B_);
    attn_f16<<<ag, 512, attn_smem>>>(q, k, v, adj, x, att);

    gemm_f16<<<M / 128, 256, gemm_smem>>>(att, W1, b1, nullptr, hbuf, 1, 0);
    gemm_f16<<<M / 128, 256, gemm_smem>>>(hbuf, W2, b2, att, out, 1, 0);
}